// round 7
// baseline (speedup 1.0000x reference)
#include <cuda_runtime.h>
#include <math.h>

#define NB 8
#define NT 8192
#define ND 2048
#define NROWS (NB * NT)
#define KSEL 2048      // NT * 0.25
#define CAND_MAX 256

// Scratch + counters (device globals; no allocations). Counters reset by
// their consumer before kernel exit -> graph-replay safe.
__device__ double d_ea[NROWS];        // exp(-bce_p * CE)   per row
__device__ double d_eb0[NROWS];       // exp(-bcu_p * D_st) per row
__device__ double d_part[NROWS / 8];  // per-CTA fp64 partial sums of D_st
__device__ double d_K;                // exp(bcu_p * m * ma)
__device__ int    d_ctr1;
__device__ int    d_ctr2[NB];

// Fast fp64 exp: Cody-Waite reduction + 13-term poly; ~1e-15 rel accuracy.
__device__ __forceinline__ double fast_exp(double x)
{
    x = fmin(fmax(x, -700.0), 700.0);
    const double LOG2E = 1.4426950408889634074;
    const double LN2HI = 6.93147180369123816490e-01;
    const double LN2LO = 1.90821492927058770002e-10;
    double k = rint(x * LOG2E);
    double r = fma(-k, LN2HI, x);
    r = fma(-k, LN2LO, r);
    double p = 2.08767569878681e-09;
    p = fma(p, r, 2.50521083854417e-08);
    p = fma(p, r, 2.75573192239859e-07);
    p = fma(p, r, 2.75573192239859e-06);
    p = fma(p, r, 2.48015873015873e-05);
    p = fma(p, r, 1.98412698412698e-04);
    p = fma(p, r, 1.38888888888889e-03);
    p = fma(p, r, 8.33333333333333e-03);
    p = fma(p, r, 4.16666666666667e-02);
    p = fma(p, r, 1.66666666666667e-01);
    p = fma(p, r, 0.5);
    p = fma(p, r, 1.0);
    p = fma(p, r, 1.0);
    long long ki = (long long)k;
    double s = __longlong_as_double((unsigned long long)(ki + 1023) << 52);
    return p * s;
}

// ---------------------------------------------------------------------------
// Kernel 1: per-row squared-norm reductions (warp-per-row, at the LTS/HBM
// cap: reads the full 1.07 GB and IS the runtime); per-row fp64 exps in a
// one-warp CTA tail (hidden under memory stalls); last-arriving CTA computes
// the global mean -> scalar K.
// ---------------------------------------------------------------------------
__global__ void __launch_bounds__(256) row_reduce_kernel(
    const float4* __restrict__ a, const float4* __restrict__ p,
    const float* __restrict__ oce, const float* __restrict__ mcu,
    const float* __restrict__ bce, const float* __restrict__ bcu)
{
    const int warp = threadIdx.x >> 5;
    const int lane = threadIdx.x & 31;
    const int row  = blockIdx.x * 8 + warp;
    const size_t base = (size_t)row * (ND / 4);

    float s_st = 0.0f, s_ch = 0.0f;
#pragma unroll
    for (int j = 0; j < 16; ++j) {
        const size_t idx = base + lane + 32 * j;
        float4 av = __ldg(&a[idx]);
        float4 pv = __ldg(&p[idx]);
        s_st += av.x * av.x + av.y * av.y + av.z * av.z + av.w * av.w;
        float dx = av.x - pv.x, dy = av.y - pv.y;
        float dz = av.z - pv.z, dw = av.w - pv.w;
        s_ch += dx * dx + dy * dy + dz * dz + dw * dw;
    }

#pragma unroll
    for (int off = 16; off > 0; off >>= 1) {
        s_st += __shfl_down_sync(0xFFFFFFFFu, s_st, off);
        s_ch += __shfl_down_sync(0xFFFFFFFFu, s_ch, off);
    }

    __shared__ float sh_dst[8], sh_dch[8];
    if (lane == 0) {
        const float invd = 1.0f / (float)ND;
        sh_dst[warp] = s_st * invd;
        sh_dch[warp] = s_ch * invd;
    }
    __syncthreads();

    // CTA tail: 8 lanes compute the 2 fp64 exps per row + CTA partial sum.
    if (threadIdx.x < 8) {
        const float xce = bce[0], xcu = bcu[0];
        const float bce_p = fmaxf(xce, 0.0f) + log1pf(expf(-fabsf(xce)));
        const float bcu_p = fmaxf(xcu, 0.0f) + log1pf(expf(-fabsf(xcu)));
        const float logoce = logf(oce[0] + 1e-10f);

        const int r = blockIdx.x * 8 + threadIdx.x;
        const double dst = (double)sh_dst[threadIdx.x];
        const double dch = (double)sh_dch[threadIdx.x];
        const double CE = dst - (dch - (double)logoce);
        d_ea[r]  = fast_exp(-(double)bce_p * CE);
        d_eb0[r] = fast_exp(-(double)bcu_p * dst);

        if (threadIdx.x == 0) {
            double ps = 0.0;
#pragma unroll
            for (int i = 0; i < 8; ++i) ps += (double)sh_dst[i];
            d_part[blockIdx.x] = ps;
        }
    }

    // last-CTA: global mean of D_st -> scalar K
    __shared__ int s_last;
    __threadfence();
    __syncthreads();
    if (threadIdx.x == 0)
        s_last = (atomicAdd(&d_ctr1, 1) == (int)gridDim.x - 1);
    __syncthreads();
    if (!s_last) return;
    __threadfence();

    const int t = threadIdx.x;
    double a0 = 0.0, a1 = 0.0, a2 = 0.0, a3 = 0.0;
#pragma unroll
    for (int j = 0; j < 8; ++j) {
        a0 += __ldcg(&d_part[t + (4 * j + 0) * 256]);
        a1 += __ldcg(&d_part[t + (4 * j + 1) * 256]);
        a2 += __ldcg(&d_part[t + (4 * j + 2) * 256]);
        a3 += __ldcg(&d_part[t + (4 * j + 3) * 256]);
    }
    double s = (a0 + a1) + (a2 + a3);
#pragma unroll
    for (int off = 16; off > 0; off >>= 1)
        s += __shfl_down_sync(0xFFFFFFFFu, s, off);
    __shared__ double ws[8];
    if (lane == 0) ws[warp] = s;
    __syncthreads();
    if (t == 0) {
        double tot = 0.0;
#pragma unroll
        for (int i = 0; i < 8; ++i) tot += ws[i];
        const double ma = tot / (double)NROWS;
        const float xcu = bcu[0];
        const float bcu_p = fmaxf(xcu, 0.0f) + log1pf(expf(-fabsf(xcu)));
        d_K = fast_exp((double)bcu_p * (double)mcu[0] * ma);
        d_ctr1 = 0;   // reset for next graph replay
    }
}

// ---------------------------------------------------------------------------
// Kernel 2: gate (exp-free, division via fp32-seeded Newton reciprocal: ~10
// DP ops vs ~35 for correctly-rounded DDIV — R6 showed the DP chain on the
// tail critical path is the cost) fused with per-batch exact top-k in the
// last-arriving CTA of each batch. Select: 2 radix passes (16 prefix bits),
// then gather the ~64 prefix-matching candidates into smem and rank-count
// the exact threshold; exact 2-pass fallback if candidates > 256.
// ---------------------------------------------------------------------------
__global__ void __launch_bounds__(1024) gate_select_kernel(float* __restrict__ out)
{
    const int b    = blockIdx.x >> 4;
    const int seg  = blockIdx.x & 15;
    const int t    = threadIdx.x;
    const int warp = t >> 5;
    const int lane = t & 31;

    // ---- gate phase: 512 elements per CTA ----
    if (t < 512) {
        const double K = d_K;
        const int idx = b * NT + seg * 512 + t;
        const double ea   = d_ea[idx];
        const double eb   = d_eb0[idx] * K;
        const double prod = ea * eb;
        const double num  = 1.0 + ea + eb;
        const double den  = num + prod;
        double g;
        if (den < 1e30) {   // always true for this data (den ~ O(10))
            double r = (double)__frcp_rn((float)den);
            r = fma(fma(-den, r, 1.0), r, r);   // Newton 1: ~2^-46
            r = fma(fma(-den, r, 1.0), r, r);   // Newton 2: ~2^-53
            g = num * r;
        } else {
            g = num / den;  // defensive exact path
        }
        out[idx] = (float)g;
    }

    // ---- handshake: last CTA of this batch runs the select ----
    __shared__ int s_last;
    __threadfence();
    __syncthreads();
    if (t == 0)
        s_last = (atomicAdd(&d_ctr2[b], 1) == 15);
    __syncthreads();
    if (!s_last) return;
    __threadfence();
    if (t == 0) d_ctr2[b] = 0;   // reset for next graph replay

    // ---- select phase ----
    __shared__ int hist[32 * 256];   // warp-private rows, 32KB
    __shared__ int warp_tot[8];
    __shared__ unsigned s_pref;
    __shared__ int s_remk, s_ce, s_c2, s_cnt;
    __shared__ unsigned s_cand[CAND_MAX];
    __shared__ unsigned s_thresh;
    __shared__ int s_need, s_ceq;

    const float* gb = out + b * NT;
    unsigned uv[8];                  // whole batch cached: 1024 thr x 8 keys
#pragma unroll
    for (int it = 0; it < 8; ++it)
        uv[it] = __float_as_uint(__ldcg(&gb[t + it * 1024]));

    if (t == 0) { s_pref = 0u; s_remk = KSEL; s_ce = 0; s_c2 = 0; s_cnt = 0; }
#pragma unroll
    for (int i = 0; i < 8; ++i) hist[t + i * 1024] = 0;
    __syncthreads();

    // -- radix passes on the top two bytes --
    for (int shift = 24; shift >= 16; shift -= 8) {
        const unsigned pref = s_pref;
        const int remk = s_remk;
        const unsigned msk = (shift == 24) ? 0u : 0xFF000000u;

        int* myhist = hist + warp * 256;
#pragma unroll
        for (int it = 0; it < 8; ++it) {
            const unsigned u = uv[it];
            const bool ok = ((u & msk) == pref);
            const int bin = (u >> shift) & 0xFF;
            const unsigned active = __ballot_sync(0xFFFFFFFFu, ok);
            if (ok) {
                const unsigned peers = __match_any_sync(active, bin);
                if (lane == (__ffs(peers) - 1))
                    myhist[bin] += __popc(peers);
            }
        }
        __syncthreads();

        int v = 0, x = 0;
        if (t < 256) {
            const int bin = 255 - t;
#pragma unroll
            for (int w = 0; w < 32; ++w) v += hist[w * 256 + bin];
            x = v;
#pragma unroll
            for (int off = 1; off < 32; off <<= 1) {
                const int y = __shfl_up_sync(0xFFFFFFFFu, x, off);
                if (lane >= off) x += y;
            }
            if (lane == 31) warp_tot[warp] = x;
        }
        __syncthreads();
        if (t < 256) {
            int offset = 0;
            for (int w = 0; w < warp; ++w) offset += warp_tot[w];
            const int cum  = x + offset;
            const int prev = cum - v;
            if (prev < remk && cum >= remk) {
                s_pref = pref | ((unsigned)(255 - t) << shift);
                s_remk = remk - prev;
                if (shift == 16) s_c2 = v;   // candidate count at 16-bit prefix
            }
        }
#pragma unroll
        for (int i = 0; i < 8; ++i) hist[t + i * 1024] = 0;  // for next pass
        __syncthreads();
    }

    const int c2        = s_c2;
    const int remk2     = s_remk;
    const unsigned pref2 = s_pref;

    if (c2 <= CAND_MAX) {
        // -- gather the prefix-matching candidates, rank-count the threshold --
#pragma unroll
        for (int it = 0; it < 8; ++it) {
            const unsigned u = uv[it];
            if ((u & 0xFFFF0000u) == pref2) {
                const int pos = atomicAdd(&s_cnt, 1);
                if (pos < CAND_MAX) s_cand[pos] = u;
            }
        }
        __syncthreads();
        if (t < c2) {
            const unsigned vi = s_cand[t];
            int greater = 0, equal = 0;
            for (int j = 0; j < c2; ++j) {
                const unsigned vj = s_cand[j];
                greater += (vj > vi);
                equal   += (vj == vi);
            }
            // order-independent -> deterministic; duplicate winners write
            // identical values (benign)
            if (greater < remk2 && remk2 <= greater + equal) {
                s_thresh = vi;
                s_need   = remk2 - greater;
                s_ceq    = equal;
            }
        }
        __syncthreads();
    } else {
        // -- exact fallback: passes over bytes 1 and 0 (hist is zeroed) --
        for (int shift = 8; shift >= 0; shift -= 8) {
            const unsigned pref = s_pref;
            const int remk = s_remk;
            const unsigned msk = 0xFFFFFFFFu << (shift + 8);

            int* myhist = hist + warp * 256;
#pragma unroll
            for (int it = 0; it < 8; ++it) {
                const unsigned u = uv[it];
                const bool ok = ((u & msk) == pref);
                const int bin = (u >> shift) & 0xFF;
                const unsigned active = __ballot_sync(0xFFFFFFFFu, ok);
                if (ok) {
                    const unsigned peers = __match_any_sync(active, bin);
                    if (lane == (__ffs(peers) - 1))
                        myhist[bin] += __popc(peers);
                }
            }
            __syncthreads();

            int v = 0, x = 0;
            if (t < 256) {
                const int bin = 255 - t;
#pragma unroll
                for (int w = 0; w < 32; ++w) v += hist[w * 256 + bin];
                x = v;
#pragma unroll
                for (int off = 1; off < 32; off <<= 1) {
                    const int y = __shfl_up_sync(0xFFFFFFFFu, x, off);
                    if (lane >= off) x += y;
                }
                if (lane == 31) warp_tot[warp] = x;
            }
            __syncthreads();
            if (t < 256) {
                int offset = 0;
                for (int w = 0; w < warp; ++w) offset += warp_tot[w];
                const int cum  = x + offset;
                const int prev = cum - v;
                if (prev < remk && cum >= remk) {
                    s_pref = pref | ((unsigned)(255 - t) << shift);
                    s_remk = remk - prev;
                    if (shift == 0) s_ce = v;
                }
            }
            if (shift > 0) {
#pragma unroll
                for (int i = 0; i < 8; ++i) hist[t + i * 1024] = 0;
            }
            __syncthreads();
        }
        if (t == 0) { s_thresh = s_pref; s_need = s_remk; s_ceq = s_ce; }
        __syncthreads();
    }

    const unsigned thresh = s_thresh;
    const int need_eq = s_need;
    const int c_eq = s_ceq;

    // ---- write binary mask (second output half) ----
    float* mout = out + NROWS + b * NT;
#pragma unroll
    for (int it = 0; it < 8; ++it) {
        const int i = t + it * 1024;
        const unsigned u = uv[it];
        float mval;
        if (u > thresh)      mval = 1.0f;
        else if (u < thresh) mval = 0.0f;
        else if (c_eq == need_eq) mval = 1.0f;          // no over-tie (common)
        else {
            // rare exact fp32 tie at threshold: lower index wins (lax.top_k)
            int r = 0;
            for (int j = 0; j < i; ++j)
                if (__float_as_uint(__ldcg(&gb[j])) == thresh) ++r;
            mval = (r < need_eq) ? 1.0f : 0.0f;
        }
        mout[i] = mval;
    }
}

// ---------------------------------------------------------------------------
extern "C" void kernel_launch(void* const* d_in, const int* in_sizes, int n_in,
                              void* d_out, int out_size)
{
    const float4* a = (const float4*)d_in[0];   // actual_residual   [8,8192,2048] f32
    const float4* p = (const float4*)d_in[1];   // predicted_residual[8,8192,2048] f32
    const float* oce = (const float*)d_in[2];
    const float* mcu = (const float*)d_in[3];
    const float* bce = (const float*)d_in[4];
    const float* bcu = (const float*)d_in[5];
    float* out = (float*)d_out;                  // [2, 8, 8192]: g then binary mask

    row_reduce_kernel<<<NROWS / 8, 256>>>(a, p, oce, mcu, bce, bcu);
    gate_select_kernel<<<NB * 16, 1024>>>(out);
}